// round 3
// baseline (speedup 1.0000x reference)
#include <cuda_runtime.h>
#include <cuda_bf16.h>
#include <math.h>

// Problem constants (fixed shapes per reference)
#define N_NODES   100000
#define N_EDGES   1600000
#define NFEAT     128
#define NHID      64
#define NCLUST    20
#define ALPHA     0.2f

// Scratch (allocation-free rule: __device__ globals)
__device__ float g_support[N_NODES * NHID];   // x @ W
__device__ float g_dinv[N_NODES];             // deg -> rsqrt(deg)

// ---------------------------------------------------------------------------
// 1) degree init: self-loop weight 1
__global__ void k_init_deg() {
    int i = blockIdx.x * blockDim.x + threadIdx.x;
    if (i < N_NODES) g_dinv[i] = 1.0f;
}

// 2) accumulate edge weights into deg[dst]   (edge_index is int32)
__global__ void k_accum_deg(const int* __restrict__ ei,
                            const float* __restrict__ ew) {
    int e = blockIdx.x * blockDim.x + threadIdx.x;
    if (e < N_EDGES) {
        int d = ei[N_EDGES + e];
        atomicAdd(&g_dinv[d], ew[e]);
    }
}

// 3) dinv = rsqrt(deg)   (deg >= 1 always, self-loop)
__global__ void k_dinv() {
    int i = blockIdx.x * blockDim.x + threadIdx.x;
    if (i < N_NODES) g_dinv[i] = rsqrtf(g_dinv[i]);
}

// ---------------------------------------------------------------------------
// 4) GEMM: support[N,64] = x[N,128] @ W[128,64]
//    64-row tile per block, 256 threads, 4x4 register blocking, K chunks of 32.
__global__ __launch_bounds__(256)
void k_gemm(const float* __restrict__ x, const float* __restrict__ W) {
    __shared__ float xs[64][33];   // [row][k]  (padded)
    __shared__ float Ws[32][64];   // [k][col]

    const int t   = threadIdx.x;
    const int tx  = t & 15;        // col chunk (0..15) -> cols tx*4..tx*4+3
    const int ty  = t >> 4;        // row chunk (0..15) -> rows ty*4..ty*4+3
    const int rowbase = blockIdx.x * 64;

    float acc[4][4];
#pragma unroll
    for (int i = 0; i < 4; i++)
#pragma unroll
        for (int j = 0; j < 4; j++) acc[i][j] = 0.0f;

    for (int kb = 0; kb < NFEAT; kb += 32) {
        // load x tile: 64 rows x 32 k
#pragma unroll
        for (int n = 0; n < 8; n++) {
            int i = t + n * 256;          // 0..2047
            int r = i >> 5, c = i & 31;
            int row = rowbase + r;
            xs[r][c] = (row < N_NODES) ? x[row * NFEAT + kb + c] : 0.0f;
        }
        // load W tile: 32 k x 64 cols
#pragma unroll
        for (int n = 0; n < 8; n++) {
            int i = t + n * 256;
            int r = i >> 6, c = i & 63;
            Ws[r][c] = W[(kb + r) * NHID + c];
        }
        __syncthreads();

#pragma unroll
        for (int kk = 0; kk < 32; kk++) {
            float a[4], bb[4];
#pragma unroll
            for (int i = 0; i < 4; i++) a[i]  = xs[ty * 4 + i][kk];
#pragma unroll
            for (int j = 0; j < 4; j++) bb[j] = Ws[kk][tx * 4 + j];
#pragma unroll
            for (int i = 0; i < 4; i++)
#pragma unroll
                for (int j = 0; j < 4; j++) acc[i][j] = fmaf(a[i], bb[j], acc[i][j]);
        }
        __syncthreads();
    }

#pragma unroll
    for (int i = 0; i < 4; i++) {
        int row = rowbase + ty * 4 + i;
        if (row < N_NODES) {
#pragma unroll
            for (int j = 0; j < 4; j++)
                g_support[row * NHID + tx * 4 + j] = acc[i][j];
        }
    }
}

// ---------------------------------------------------------------------------
// 5) init z = b + dinv[i]^2 * support[i]   (self-loop contribution)
__global__ void k_zinit(const float* __restrict__ b, float* __restrict__ z) {
    int idx = blockIdx.x * blockDim.x + threadIdx.x;
    if (idx < N_NODES * NHID) {
        int n = idx >> 6, h = idx & 63;
        float di = g_dinv[n];
        z[idx] = b[h] + di * di * g_support[idx];
    }
}

// 6) edge scatter: z[dst] += norm * support[src]
//    16 threads per edge, float4 gather + 4 scalar atomics each.
__global__ __launch_bounds__(256)
void k_scatter(const int* __restrict__ ei,
               const float* __restrict__ ew,
               float* __restrict__ z) {
    long long idx = (long long)blockIdx.x * blockDim.x + threadIdx.x;
    if (idx >= (long long)N_EDGES * 16) return;
    int e = (int)(idx >> 4);
    int l = (int)(idx & 15);

    int s = ei[e];
    int d = ei[N_EDGES + e];
    float nrm = g_dinv[s] * ew[e] * g_dinv[d];

    const float4* sup4 = reinterpret_cast<const float4*>(g_support);
    float4 v = sup4[(size_t)s * 16 + l];

    float* zp = z + (size_t)d * NHID + l * 4;
    atomicAdd(zp + 0, v.x * nrm);
    atomicAdd(zp + 1, v.y * nrm);
    atomicAdd(zp + 2, v.z * nrm);
    atomicAdd(zp + 3, v.w * nrm);
}

// ---------------------------------------------------------------------------
// 7) DEC head: q[n,c] from z and mu.  128 nodes per 128-thread block.
__global__ __launch_bounds__(128)
void k_dec(const float* __restrict__ z, const float* __restrict__ mu,
           float* __restrict__ q) {
    __shared__ float zs[128][65];          // [node][dim], padded
    __shared__ float mt[NHID * NCLUST];    // transposed mu: mt[k*20 + c]

    const int t = threadIdx.x;
    const int n0 = blockIdx.x * 128;

    // load transposed mu
    for (int i = t; i < NHID * NCLUST; i += 128) {
        int k = i / NCLUST, c = i % NCLUST;
        mt[k * NCLUST + c] = mu[c * NHID + k];
    }
    // load z tile coalesced: 128 rows x 64 dims
    for (int i = t; i < 128 * NHID; i += 128) {
        int r = i >> 6, k = i & 63;
        int row = n0 + r;
        zs[r][k] = (row < N_NODES) ? z[(size_t)row * NHID + k] : 0.0f;
    }
    __syncthreads();

    int node = n0 + t;
    if (node >= N_NODES) return;

    float acc[NCLUST];
#pragma unroll
    for (int c = 0; c < NCLUST; c++) acc[c] = 0.0f;

#pragma unroll 4
    for (int k = 0; k < NHID; k++) {
        float zv = zs[t][k];
        const float4* m4 = reinterpret_cast<const float4*>(&mt[k * NCLUST]);
#pragma unroll
        for (int m = 0; m < 5; m++) {
            float4 mv = m4[m];
            float d0 = zv - mv.x, d1 = zv - mv.y, d2 = zv - mv.z, d3 = zv - mv.w;
            acc[4 * m + 0] = fmaf(d0, d0, acc[4 * m + 0]);
            acc[4 * m + 1] = fmaf(d1, d1, acc[4 * m + 1]);
            acc[4 * m + 2] = fmaf(d2, d2, acc[4 * m + 2]);
            acc[4 * m + 3] = fmaf(d3, d3, acc[4 * m + 3]);
        }
    }

    float sum = 0.0f;
    float qv[NCLUST];
#pragma unroll
    for (int c = 0; c < NCLUST; c++) {
        float base = 1.0f / (1.0f + acc[c] * (1.0f / ALPHA) + 1e-8f);
        float p = __powf(base, ALPHA + 1.0f) * 0.5f;
        qv[c] = p;
        sum += p;
    }
    float inv = 1.0f / sum;
#pragma unroll
    for (int c = 0; c < NCLUST; c++)
        q[(size_t)node * NCLUST + c] = qv[c] * inv;
}

// ---------------------------------------------------------------------------
extern "C" void kernel_launch(void* const* d_in, const int* in_sizes, int n_in,
                              void* d_out, int out_size) {
    const float* x  = (const float*)d_in[0];
    const int*   ei = (const int*)d_in[1];    // int32 (JAX x64 disabled)
    const float* ew = (const float*)d_in[2];
    const float* W  = (const float*)d_in[3];
    const float* b  = (const float*)d_in[4];
    const float* mu = (const float*)d_in[5];

    float* z = (float*)d_out;                           // [N, 64]
    float* q = (float*)d_out + (size_t)N_NODES * NHID;  // [N, 20]

    k_init_deg<<<(N_NODES + 255) / 256, 256>>>();
    k_accum_deg<<<(N_EDGES + 255) / 256, 256>>>(ei, ew);
    k_dinv<<<(N_NODES + 255) / 256, 256>>>();
    k_gemm<<<(N_NODES + 63) / 64, 256>>>(x, W);
    k_zinit<<<(N_NODES * NHID + 255) / 256, 256>>>(b, z);
    {
        long long total = (long long)N_EDGES * 16;
        int blocks = (int)((total + 255) / 256);
        k_scatter<<<blocks, 256>>>(ei, ew, z);
    }
    k_dec<<<(N_NODES + 127) / 128, 128>>>(z, mu, q);
}

// round 4
// speedup vs baseline: 1.0052x; 1.0052x over previous
#include <cuda_runtime.h>
#include <cuda_bf16.h>
#include <math.h>

// Problem constants (fixed shapes per reference)
#define N_NODES   100000
#define N_EDGES   1600000
#define NFEAT     128
#define NHID      64
#define NCLUST    20
#define ALPHA     0.2f

// Scratch (allocation-free rule: __device__ globals)
__device__ float g_support[N_NODES * NHID];   // x @ W
__device__ float g_dinv[N_NODES];             // deg -> rsqrt(deg)

// ---------------------------------------------------------------------------
// 1) degree init: self-loop weight 1
__global__ void k_init_deg() {
    int i = blockIdx.x * blockDim.x + threadIdx.x;
    if (i < N_NODES) g_dinv[i] = 1.0f;
}

// 2) accumulate edge weights into deg[dst]   (edge_index is int32)
__global__ void k_accum_deg(const int* __restrict__ ei,
                            const float* __restrict__ ew) {
    int e = blockIdx.x * blockDim.x + threadIdx.x;
    if (e < N_EDGES) {
        int d = ei[N_EDGES + e];
        atomicAdd(&g_dinv[d], ew[e]);
    }
}

// 3) dinv = rsqrt(deg)   (deg >= 1 always, self-loop)
__global__ void k_dinv() {
    int i = blockIdx.x * blockDim.x + threadIdx.x;
    if (i < N_NODES) g_dinv[i] = rsqrtf(g_dinv[i]);
}

// ---------------------------------------------------------------------------
// 4) GEMM: support[N,64] = x[N,128] @ W[128,64]
//    64-row tile per block, 256 threads, 4x4 register blocking, K chunks of 32.
__global__ __launch_bounds__(256)
void k_gemm(const float* __restrict__ x, const float* __restrict__ W) {
    __shared__ float xs[64][33];   // [row][k]  (padded)
    __shared__ float Ws[32][64];   // [k][col]

    const int t   = threadIdx.x;
    const int tx  = t & 15;        // col chunk (0..15) -> cols tx*4..tx*4+3
    const int ty  = t >> 4;        // row chunk (0..15) -> rows ty*4..ty*4+3
    const int rowbase = blockIdx.x * 64;

    float acc[4][4];
#pragma unroll
    for (int i = 0; i < 4; i++)
#pragma unroll
        for (int j = 0; j < 4; j++) acc[i][j] = 0.0f;

    for (int kb = 0; kb < NFEAT; kb += 32) {
        // load x tile: 64 rows x 32 k
#pragma unroll
        for (int n = 0; n < 8; n++) {
            int i = t + n * 256;          // 0..2047
            int r = i >> 5, c = i & 31;
            int row = rowbase + r;
            xs[r][c] = (row < N_NODES) ? x[row * NFEAT + kb + c] : 0.0f;
        }
        // load W tile: 32 k x 64 cols
#pragma unroll
        for (int n = 0; n < 8; n++) {
            int i = t + n * 256;
            int r = i >> 6, c = i & 63;
            Ws[r][c] = W[(kb + r) * NHID + c];
        }
        __syncthreads();

#pragma unroll
        for (int kk = 0; kk < 32; kk++) {
            float a[4], bb[4];
#pragma unroll
            for (int i = 0; i < 4; i++) a[i]  = xs[ty * 4 + i][kk];
#pragma unroll
            for (int j = 0; j < 4; j++) bb[j] = Ws[kk][tx * 4 + j];
#pragma unroll
            for (int i = 0; i < 4; i++)
#pragma unroll
                for (int j = 0; j < 4; j++) acc[i][j] = fmaf(a[i], bb[j], acc[i][j]);
        }
        __syncthreads();
    }

#pragma unroll
    for (int i = 0; i < 4; i++) {
        int row = rowbase + ty * 4 + i;
        if (row < N_NODES) {
#pragma unroll
            for (int j = 0; j < 4; j++)
                g_support[row * NHID + tx * 4 + j] = acc[i][j];
        }
    }
}

// ---------------------------------------------------------------------------
// 5) init z = b + dinv[i]^2 * support[i]   (self-loop contribution)
__global__ void k_zinit(const float* __restrict__ b, float* __restrict__ z) {
    int idx = blockIdx.x * blockDim.x + threadIdx.x;
    if (idx < N_NODES * NHID) {
        int n = idx >> 6, h = idx & 63;
        float di = g_dinv[n];
        z[idx] = b[h] + di * di * g_support[idx];
    }
}

// 6) edge scatter: z[dst] += norm * support[src]
//    16 threads per edge, float4 gather + 4 scalar atomics each.
__global__ __launch_bounds__(256)
void k_scatter(const int* __restrict__ ei,
               const float* __restrict__ ew,
               float* __restrict__ z) {
    long long idx = (long long)blockIdx.x * blockDim.x + threadIdx.x;
    if (idx >= (long long)N_EDGES * 16) return;
    int e = (int)(idx >> 4);
    int l = (int)(idx & 15);

    int s = ei[e];
    int d = ei[N_EDGES + e];
    float nrm = g_dinv[s] * ew[e] * g_dinv[d];

    const float4* sup4 = reinterpret_cast<const float4*>(g_support);
    float4 v = sup4[(size_t)s * 16 + l];

    float* zp = z + (size_t)d * NHID + l * 4;
    atomicAdd(zp + 0, v.x * nrm);
    atomicAdd(zp + 1, v.y * nrm);
    atomicAdd(zp + 2, v.z * nrm);
    atomicAdd(zp + 3, v.w * nrm);
}

// ---------------------------------------------------------------------------
// 7) DEC head: q[n,c] from z and mu.  128 nodes per 128-thread block.
__global__ __launch_bounds__(128)
void k_dec(const float* __restrict__ z, const float* __restrict__ mu,
           float* __restrict__ q) {
    __shared__ float zs[128][65];          // [node][dim], padded
    __shared__ float mt[NHID * NCLUST];    // transposed mu: mt[k*20 + c]

    const int t = threadIdx.x;
    const int n0 = blockIdx.x * 128;

    // load transposed mu
    for (int i = t; i < NHID * NCLUST; i += 128) {
        int k = i / NCLUST, c = i % NCLUST;
        mt[k * NCLUST + c] = mu[c * NHID + k];
    }
    // load z tile coalesced: 128 rows x 64 dims
    for (int i = t; i < 128 * NHID; i += 128) {
        int r = i >> 6, k = i & 63;
        int row = n0 + r;
        zs[r][k] = (row < N_NODES) ? z[(size_t)row * NHID + k] : 0.0f;
    }
    __syncthreads();

    int node = n0 + t;
    if (node >= N_NODES) return;

    float acc[NCLUST];
#pragma unroll
    for (int c = 0; c < NCLUST; c++) acc[c] = 0.0f;

#pragma unroll 4
    for (int k = 0; k < NHID; k++) {
        float zv = zs[t][k];
        const float4* m4 = reinterpret_cast<const float4*>(&mt[k * NCLUST]);
#pragma unroll
        for (int m = 0; m < 5; m++) {
            float4 mv = m4[m];
            float d0 = zv - mv.x, d1 = zv - mv.y, d2 = zv - mv.z, d3 = zv - mv.w;
            acc[4 * m + 0] = fmaf(d0, d0, acc[4 * m + 0]);
            acc[4 * m + 1] = fmaf(d1, d1, acc[4 * m + 1]);
            acc[4 * m + 2] = fmaf(d2, d2, acc[4 * m + 2]);
            acc[4 * m + 3] = fmaf(d3, d3, acc[4 * m + 3]);
        }
    }

    float sum = 0.0f;
    float qv[NCLUST];
#pragma unroll
    for (int c = 0; c < NCLUST; c++) {
        float base = 1.0f / (1.0f + acc[c] * (1.0f / ALPHA) + 1e-8f);
        float p = __powf(base, ALPHA + 1.0f) * 0.5f;
        qv[c] = p;
        sum += p;
    }
    float inv = 1.0f / sum;
#pragma unroll
    for (int c = 0; c < NCLUST; c++)
        q[(size_t)node * NCLUST + c] = qv[c] * inv;
}

// ---------------------------------------------------------------------------
extern "C" void kernel_launch(void* const* d_in, const int* in_sizes, int n_in,
                              void* d_out, int out_size) {
    const float* x  = (const float*)d_in[0];
    const int*   ei = (const int*)d_in[1];    // int32 (JAX x64 disabled)
    const float* ew = (const float*)d_in[2];
    const float* W  = (const float*)d_in[3];
    const float* b  = (const float*)d_in[4];
    const float* mu = (const float*)d_in[5];

    float* z = (float*)d_out;                           // [N, 64]
    float* q = (float*)d_out + (size_t)N_NODES * NHID;  // [N, 20]

    k_init_deg<<<(N_NODES + 255) / 256, 256>>>();
    k_accum_deg<<<(N_EDGES + 255) / 256, 256>>>(ei, ew);
    k_dinv<<<(N_NODES + 255) / 256, 256>>>();
    k_gemm<<<(N_NODES + 63) / 64, 256>>>(x, W);
    k_zinit<<<(N_NODES * NHID + 255) / 256, 256>>>(b, z);
    {
        long long total = (long long)N_EDGES * 16;
        int blocks = (int)((total + 255) / 256);
        k_scatter<<<blocks, 256>>>(ei, ew, z);
    }
    k_dec<<<(N_NODES + 127) / 128, 128>>>(z, mu, q);
}